// round 14
// baseline (speedup 1.0000x reference)
#include <cuda_runtime.h>
#include <cuda_fp16.h>
#include <math.h>

#define NN   50000
#define EE   800000
#define IN_DIM 128
#define O1   64
#define O2   128

#define SCAN_B 1024
#define NBLK   ((NN + SCAN_B - 1) / SCAN_B)   // 49

#define PREP_BLOCKS ((EE + 255) / 256)        // 3125
#define G1_BLOCKS   ((NN + 63) / 64)          // 782
#define AGG1_BLOCKS ((NN / 2 * 32 + 255) / 256) // 3125 (2 nodes/warp, split edges)
#define AGG2_BLOCKS ((NN * 32 + 255) / 256)     // 6250 (1 node/warp, split edges)
#define RST_BLOCKS  98                        // zero g_dc (2 ULL/thread) + g_lk
#define FILL_BLOCKS ((EE / 4 + 255) / 256)    // 782 (4 edges per thread)

#define DEG_SCALE 1048576.0f                  // 2^20 fixed point for edge-weight sums

// Scratch (device globals — no allocation allowed). Index 0/1 = tower.
__device__ unsigned long long g_dc[2][NN];    // hi32 = count, lo32 = fixedpoint sum(relu(w))
__device__ unsigned long long g_lk[2][64];    // lookback: hi32 flag (0/1/2), lo32 value
__device__ float  g_dinv[2][NN];
__device__ int    g_off [2][NN + 1];          // exclusive offsets (immutable after scan)
__device__ int    g_rank[2][EE];              // per-edge rank within its dst bucket
__device__ int2   g_edge[2][EE];              // (src, half2(norm,norm) bits)
__device__ __half g_h1h[2][NN * O1];          // layer-1 hidden fp16 (gather-bound)
__device__ float  g_z1 [2][NN * O1];
__device__ __half g_h2h[2][NN * O2];          // layer-2 hidden fp16 (gather-bound)

// ---------------------------------------------------------------------------
// packed fp32x2 FMA (sm_103a FFMA2)
// ---------------------------------------------------------------------------
__device__ __forceinline__ void ffma2(float2& acc, float2 a, float2 w) {
    unsigned long long ac, av, wv;
    ac = *(unsigned long long*)&acc;
    av = *(unsigned long long*)&a;
    wv = *(unsigned long long*)&w;
    asm("fma.rn.f32x2 %0, %1, %2, %0;" : "+l"(ac) : "l"(av), "l"(wv));
    acc = *(float2*)&ac;
}

__device__ __forceinline__ __half2 shfl16_hmax2(__half2 v) {
    unsigned u = *(unsigned*)&v;
    unsigned o = __shfl_xor_sync(0xffffffffu, u, 16);
    return __hmax2(v, *(__half2*)&o);
}

// ---------------------------------------------------------------------------
// Register-tiled GEMM body: C[64-row tile, 64-col tile] = A[N,K] @ W[K,OC]
// ---------------------------------------------------------------------------
template<int K, int OC>
__device__ __forceinline__ void gemm_body(const float* __restrict__ A,
                                          const float* __restrict__ W,
                                          __half* __restrict__ C,
                                          int rowBlk, int colBase, int tid) {
    __shared__ float2 Wp[(K / 2) * 64];
    int tx = tid & 15;
    int ty = tid >> 4;
    for (int idx = tid; idx < (K / 2) * 64; idx += 256) {
        int kp = idx >> 6, c = idx & 63;
        Wp[idx] = make_float2(W[(2 * kp)     * OC + colBase + c],
                              W[(2 * kp + 1) * OC + colBase + c]);
    }
    __syncthreads();

    int r0 = rowBlk * 64 + ty * 4;
    int c0 = tx * 4;
    float2 acc[4][4];
#pragma unroll
    for (int i = 0; i < 4; i++)
#pragma unroll
        for (int j = 0; j < 4; j++) acc[i][j] = make_float2(0.0f, 0.0f);

#pragma unroll 4
    for (int kk = 0; kk < K; kk += 4) {
        float4 a[4];
#pragma unroll
        for (int i = 0; i < 4; i++) {
            int r = r0 + i;
            a[i] = (r < NN) ? *(const float4*)(A + (size_t)r * K + kk)
                            : make_float4(0.0f, 0.0f, 0.0f, 0.0f);
        }
#pragma unroll
        for (int kp = 0; kp < 2; kp++) {
            const float2* wrow = Wp + ((kk >> 1) + kp) * 64 + c0;
            float4 wA = *(const float4*)(wrow);
            float4 wB = *(const float4*)(wrow + 2);
            float2 w0 = make_float2(wA.x, wA.y);
            float2 w1 = make_float2(wA.z, wA.w);
            float2 w2 = make_float2(wB.x, wB.y);
            float2 w3 = make_float2(wB.z, wB.w);
#pragma unroll
            for (int i = 0; i < 4; i++) {
                float2 ap = kp ? make_float2(a[i].z, a[i].w)
                               : make_float2(a[i].x, a[i].y);
                ffma2(acc[i][0], ap, w0);
                ffma2(acc[i][1], ap, w1);
                ffma2(acc[i][2], ap, w2);
                ffma2(acc[i][3], ap, w3);
            }
        }
    }
#pragma unroll
    for (int i = 0; i < 4; i++) {
        int r = r0 + i;
        if (r < NN) {
            __half2 p0 = __floats2half2_rn(acc[i][0].x + acc[i][0].y,
                                           acc[i][1].x + acc[i][1].y);
            __half2 p1 = __floats2half2_rn(acc[i][2].x + acc[i][2].y,
                                           acc[i][3].x + acc[i][3].y);
            uint2 pk;
            pk.x = *(unsigned*)&p0;
            pk.y = *(unsigned*)&p1;
            *(uint2*)(C + (size_t)r * OC + colBase + c0) = pk;
        }
    }
}

// ---------------------------------------------------------------------------
// fused: packed deg/count atomics + rank capture | GEMM1
// ---------------------------------------------------------------------------
__global__ void k_prep_gemm1(const int* __restrict__ ei1, const float* __restrict__ ew1,
                             const int* __restrict__ ei2, const float* __restrict__ ew2,
                             const float* __restrict__ x1, const float* __restrict__ x2,
                             const float* __restrict__ W1) {
    int tw = blockIdx.y;
    if (blockIdx.x < PREP_BLOCKS) {
        const int*   ei = tw ? ei2 : ei1;
        const float* ew = tw ? ew2 : ew1;
        int e = blockIdx.x * 256 + threadIdx.x;
        if (e < EE) {
            int d = ei[EE + e];
            float w = fmaxf(ew[e], 0.0f);          // relu(edge_weight)
            unsigned long long pk =
                (1ULL << 32) | (unsigned long long)__float2uint_rn(w * DEG_SCALE);
            unsigned long long old = atomicAdd(&g_dc[tw][d], pk);
            g_rank[tw][e] = (int)(old >> 32);      // rank within dst bucket
        }
    } else {
        gemm_body<IN_DIM, O1>(tw ? x2 : x1, W1, g_h1h[tw],
                              blockIdx.x - PREP_BLOCKS, 0, threadIdx.x);
    }
}

// ---------------------------------------------------------------------------
// single-pass scan (decoupled lookback) + dinv. grid (NBLK,2) x 1024 threads
// ---------------------------------------------------------------------------
__global__ void k_scan() {
    int tw   = blockIdx.y;
    int b    = blockIdx.x;
    int i    = b * SCAN_B + threadIdx.x;
    int lane = threadIdx.x & 31;
    int wid  = threadIdx.x >> 5;
    unsigned long long dc = (i < NN) ? g_dc[tw][i] : 0ULL;
    int c = (int)(dc >> 32);
    int v = c;
#pragma unroll
    for (int d = 1; d < 32; d <<= 1) {
        int t = __shfl_up_sync(0xffffffffu, v, d);
        if (lane >= d) v += t;
    }
    __shared__ int wsum[32];
    if (lane == 31) wsum[wid] = v;
    __syncthreads();
    if (wid == 0) {
        int w = wsum[lane];
#pragma unroll
        for (int d = 1; d < 32; d <<= 1) {
            int t = __shfl_up_sync(0xffffffffu, w, d);
            if (lane >= d) w += t;
        }
        wsum[lane] = w;
    }
    __syncthreads();
    int add = (wid > 0) ? wsum[wid - 1] : 0;
    int incl = v + add;
    int total = wsum[31];

    __shared__ int s_exc;
    if (threadIdx.x == 0) {
        unsigned long long flag = (b == 0) ? 2ULL : 1ULL;
        atomicExch(&g_lk[tw][b], (flag << 32) | (unsigned)total);
        int exc = 0;
        if (b > 0) {
            int p = b - 1;
            while (true) {
                unsigned long long pv = *((volatile unsigned long long*)&g_lk[tw][p]);
                unsigned f = (unsigned)(pv >> 32);
                if (f == 2u) { exc += (int)(unsigned)pv; break; }
                if (f == 1u) { exc += (int)(unsigned)pv; p--; }
            }
            atomicExch(&g_lk[tw][b], (2ULL << 32) | (unsigned)(total + exc));
        }
        s_exc = exc;
    }
    __syncthreads();
    if (i < NN) {
        g_off[tw][i] = s_exc + incl - c;
        float deg = 2.0f + (float)(unsigned)dc * (1.0f / DEG_SCALE);
        g_dinv[tw][i] = rsqrtf(deg);
    }
    if (b == gridDim.x - 1 && threadIdx.x == 0) g_off[tw][NN] = EE;
}

// ---------------------------------------------------------------------------
// fill: atomic-free, 4 edges per thread (vectorized coalesced loads)
// ---------------------------------------------------------------------------
__global__ void k_fill(const int* __restrict__ ei1, const float* __restrict__ ew1,
                       const int* __restrict__ ei2, const float* __restrict__ ew2) {
    int tw = blockIdx.y;
    const int*   ei = tw ? ei2 : ei1;
    const float* ew = tw ? ew2 : ew1;
    int e0 = (blockIdx.x * 256 + threadIdx.x) * 4;
    if (e0 >= EE) return;
    int4   sv = *(const int4*)(ei + e0);
    int4   dv = *(const int4*)(ei + EE + e0);
    float4 wv = *(const float4*)(ew + e0);
    int4   rv = *(const int4*)(g_rank[tw] + e0);
    const float* dinv = g_dinv[tw];
    int2* edge = g_edge[tw];
    const int* off = g_off[tw];
    {
        float nrm = dinv[sv.x] * fmaxf(wv.x, 0.0f) * dinv[dv.x];
        __half2 nh = __float2half2_rn(nrm);
        edge[off[dv.x] + rv.x] = make_int2(sv.x, *(int*)&nh);
    }
    {
        float nrm = dinv[sv.y] * fmaxf(wv.y, 0.0f) * dinv[dv.y];
        __half2 nh = __float2half2_rn(nrm);
        edge[off[dv.y] + rv.y] = make_int2(sv.y, *(int*)&nh);
    }
    {
        float nrm = dinv[sv.z] * fmaxf(wv.z, 0.0f) * dinv[dv.z];
        __half2 nh = __float2half2_rn(nrm);
        edge[off[dv.z] + rv.z] = make_int2(sv.z, *(int*)&nh);
    }
    {
        float nrm = dinv[sv.w] * fmaxf(wv.w, 0.0f) * dinv[dv.w];
        __half2 nh = __float2half2_rn(nrm);
        edge[off[dv.w] + rv.w] = make_int2(sv.w, *(int*)&nh);
    }
}

__global__ void k_gemm2(const float* __restrict__ W2) {
    int tw = blockIdx.z;
    gemm_body<O1, O2>(g_z1[tw], W2, g_h2h[tw],
                      blockIdx.x, blockIdx.y * 64, threadIdx.y * 16 + threadIdx.x);
}

// ---------------------------------------------------------------------------
// Aggregation 1: 2 nodes per warp, each node's edges split across the two
// half-warps (8-lane quads hold the 64-feature row); combine via shfl_xor(16)
// ---------------------------------------------------------------------------
__global__ void k_aggr1(const float* __restrict__ b1) {
    int tw    = blockIdx.y;
    int gwarp = (blockIdx.x * blockDim.x + threadIdx.x) >> 5;
    int lane  = threadIdx.x & 31;
    int grp   = lane >> 4;            // which edge half
    int node  = gwarp * 2 + ((lane >> 3) & 1);
    int ln    = lane & 7;
    if (node >= NN) return;
    const int2*   eg = g_edge[tw];
    const __half* h  = g_h1h[tw];
    int beg = g_off[tw][node];
    int end = g_off[tw][node + 1];
    float dv = g_dinv[tw][node];
    __half2 slh = __float2half2_rn(2.0f * dv * dv);
    uint4 selfpk = *(const uint4*)(h + (size_t)node * O1 + ln * 8);
    __half2 mA = __hmul2(*(__half2*)&selfpk.x, slh);
    __half2 mB = __hmul2(*(__half2*)&selfpk.y, slh);
    __half2 mC = __hmul2(*(__half2*)&selfpk.z, slh);
    __half2 mD = __hmul2(*(__half2*)&selfpk.w, slh);
    int j = beg + grp;
    for (; j + 2 < end; j += 4) {     // edges j and j+2 (this group's stride-2 stream)
        int2 e0 = eg[j], e1 = eg[j + 2];
        uint4 v0 = *(const uint4*)(h + (size_t)e0.x * O1 + ln * 8);
        uint4 v1 = *(const uint4*)(h + (size_t)e1.x * O1 + ln * 8);
        __half2 w0 = *(__half2*)&e0.y, w1 = *(__half2*)&e1.y;
        mA = __hmax2(mA, __hmul2(*(__half2*)&v0.x, w0));
        mB = __hmax2(mB, __hmul2(*(__half2*)&v0.y, w0));
        mC = __hmax2(mC, __hmul2(*(__half2*)&v0.z, w0));
        mD = __hmax2(mD, __hmul2(*(__half2*)&v0.w, w0));
        mA = __hmax2(mA, __hmul2(*(__half2*)&v1.x, w1));
        mB = __hmax2(mB, __hmul2(*(__half2*)&v1.y, w1));
        mC = __hmax2(mC, __hmul2(*(__half2*)&v1.z, w1));
        mD = __hmax2(mD, __hmul2(*(__half2*)&v1.w, w1));
    }
    if (j < end) {
        int2 e = eg[j];
        uint4 v = *(const uint4*)(h + (size_t)e.x * O1 + ln * 8);
        __half2 wh = *(__half2*)&e.y;
        mA = __hmax2(mA, __hmul2(*(__half2*)&v.x, wh));
        mB = __hmax2(mB, __hmul2(*(__half2*)&v.y, wh));
        mC = __hmax2(mC, __hmul2(*(__half2*)&v.z, wh));
        mD = __hmax2(mD, __hmul2(*(__half2*)&v.w, wh));
    }
    // combine the two edge halves (lane^16 has same node, same ln)
    mA = shfl16_hmax2(mA);
    mB = shfl16_hmax2(mB);
    mC = shfl16_hmax2(mC);
    mD = shfl16_hmax2(mD);
    if (grp == 0) {
        float2 fA = __half22float2(mA);
        float2 fB = __half22float2(mB);
        float2 fC = __half22float2(mC);
        float2 fD = __half22float2(mD);
        float m[8] = {fA.x, fA.y, fB.x, fB.y, fC.x, fC.y, fD.x, fD.y};
#pragma unroll
        for (int q = 0; q < 8; q++)
            if (!isfinite(m[q])) m[q] = 0.0f;
        float4 bv0 = *(const float4*)(b1 + ln * 8);
        float4 bv1 = *(const float4*)(b1 + ln * 8 + 4);
        float* dst = g_z1[tw] + (size_t)node * O1 + ln * 8;
        *(float4*)(dst)     = make_float4(m[0] + bv0.x, m[1] + bv0.y, m[2] + bv0.z, m[3] + bv0.w);
        *(float4*)(dst + 4) = make_float4(m[4] + bv1.x, m[5] + bv1.y, m[6] + bv1.z, m[7] + bv1.w);
    }
}

// ---------------------------------------------------------------------------
// Aggregation 2: 1 node per warp, edges split across the two half-warps
// (16 lanes x uint4 hold the 128-feature row); combine via shfl_xor(16);
// tail blocks reset g_dc / g_lk for the next invocation
// ---------------------------------------------------------------------------
__global__ void k_aggr2(const float* __restrict__ b2, float* __restrict__ out) {
    int tw = blockIdx.y;
    if (blockIdx.x >= AGG2_BLOCKS) {
        int rb  = blockIdx.x - AGG2_BLOCKS;
        int idx = (rb * 256 + threadIdx.x) * 2;
        if (idx     < NN) g_dc[tw][idx]     = 0ULL;
        if (idx + 1 < NN) g_dc[tw][idx + 1] = 0ULL;
        if (rb == 0 && threadIdx.x < 64) g_lk[tw][threadIdx.x] = 0ULL;
        return;
    }
    int node = (blockIdx.x * blockDim.x + threadIdx.x) >> 5;
    int lane = threadIdx.x & 31;
    int grp  = lane >> 4;
    int ln   = lane & 15;
    if (node >= NN) return;
    const int2*   eg = g_edge[tw];
    const __half* h  = g_h2h[tw];
    float* op = out + (size_t)tw * NN * O2;
    int beg = g_off[tw][node];
    int end = g_off[tw][node + 1];
    float dv = g_dinv[tw][node];
    __half2 slh = __float2half2_rn(2.0f * dv * dv);
    uint4 selfpk = *(const uint4*)(h + (size_t)node * O2 + ln * 8);
    __half2 mA = __hmul2(*(__half2*)&selfpk.x, slh);
    __half2 mB = __hmul2(*(__half2*)&selfpk.y, slh);
    __half2 mC = __hmul2(*(__half2*)&selfpk.z, slh);
    __half2 mD = __hmul2(*(__half2*)&selfpk.w, slh);
    int j = beg + grp;
    for (; j + 2 < end; j += 4) {
        int2 e0 = eg[j], e1 = eg[j + 2];
        uint4 v0 = *(const uint4*)(h + (size_t)e0.x * O2 + ln * 8);
        uint4 v1 = *(const uint4*)(h + (size_t)e1.x * O2 + ln * 8);
        __half2 w0 = *(__half2*)&e0.y, w1 = *(__half2*)&e1.y;
        mA = __hmax2(mA, __hmul2(*(__half2*)&v0.x, w0));
        mB = __hmax2(mB, __hmul2(*(__half2*)&v0.y, w0));
        mC = __hmax2(mC, __hmul2(*(__half2*)&v0.z, w0));
        mD = __hmax2(mD, __hmul2(*(__half2*)&v0.w, w0));
        mA = __hmax2(mA, __hmul2(*(__half2*)&v1.x, w1));
        mB = __hmax2(mB, __hmul2(*(__half2*)&v1.y, w1));
        mC = __hmax2(mC, __hmul2(*(__half2*)&v1.z, w1));
        mD = __hmax2(mD, __hmul2(*(__half2*)&v1.w, w1));
    }
    if (j < end) {
        int2 e = eg[j];
        uint4 v = *(const uint4*)(h + (size_t)e.x * O2 + ln * 8);
        __half2 wh = *(__half2*)&e.y;
        mA = __hmax2(mA, __hmul2(*(__half2*)&v.x, wh));
        mB = __hmax2(mB, __hmul2(*(__half2*)&v.y, wh));
        mC = __hmax2(mC, __hmul2(*(__half2*)&v.z, wh));
        mD = __hmax2(mD, __hmul2(*(__half2*)&v.w, wh));
    }
    mA = shfl16_hmax2(mA);
    mB = shfl16_hmax2(mB);
    mC = shfl16_hmax2(mC);
    mD = shfl16_hmax2(mD);
    if (grp == 0) {
        float2 fA = __half22float2(mA);
        float2 fB = __half22float2(mB);
        float2 fC = __half22float2(mC);
        float2 fD = __half22float2(mD);
        float m[8] = {fA.x, fA.y, fB.x, fB.y, fC.x, fC.y, fD.x, fD.y};
#pragma unroll
        for (int q = 0; q < 8; q++)
            if (!isfinite(m[q])) m[q] = 0.0f;
        float4 bv0 = *(const float4*)(b2 + ln * 8);
        float4 bv1 = *(const float4*)(b2 + ln * 8 + 4);
        float* dst = op + (size_t)node * O2 + ln * 8;
        *(float4*)(dst)     = make_float4(m[0] + bv0.x, m[1] + bv0.y, m[2] + bv0.z, m[3] + bv0.w);
        *(float4*)(dst + 4) = make_float4(m[4] + bv1.x, m[5] + bv1.y, m[6] + bv1.z, m[7] + bv1.w);
    }
}

// ---------------------------------------------------------------------------
// launch
// ---------------------------------------------------------------------------
extern "C" void kernel_launch(void* const* d_in, const int* in_sizes, int n_in,
                              void* d_out, int out_size) {
    const float* x1  = (const float*)d_in[0];
    const int*   ei1 = (const int*)  d_in[1];
    const float* ew1 = (const float*)d_in[2];
    const float* x2  = (const float*)d_in[3];
    const int*   ei2 = (const int*)  d_in[4];
    const float* ew2 = (const float*)d_in[5];
    const float* W1  = (const float*)d_in[6];
    const float* b1  = (const float*)d_in[7];
    const float* W2  = (const float*)d_in[8];
    const float* b2  = (const float*)d_in[9];
    float* out = (float*)d_out;

    const int TB = 256;
    k_prep_gemm1<<<dim3(PREP_BLOCKS + G1_BLOCKS, 2), TB>>>(ei1, ew1, ei2, ew2, x1, x2, W1);
    k_scan      <<<dim3(NBLK, 2), SCAN_B>>>();
    k_fill      <<<dim3(FILL_BLOCKS, 2), TB>>>(ei1, ew1, ei2, ew2);

    k_aggr1<<<dim3(AGG1_BLOCKS, 2), TB>>>(b1);
    dim3 gblk(16, 16);
    k_gemm2<<<dim3(G1_BLOCKS, 2, 2), gblk>>>(W2);
    k_aggr2<<<dim3(AGG2_BLOCKS + RST_BLOCKS, 2), TB>>>(b2, out);
}

// round 15
// speedup vs baseline: 1.0538x; 1.0538x over previous
#include <cuda_runtime.h>
#include <cuda_fp16.h>
#include <math.h>

#define NN   50000
#define EE   800000
#define IN_DIM 128
#define O1   64
#define O2   128

#define SCAN_B 1024
#define NBLK   ((NN + SCAN_B - 1) / SCAN_B)   // 49

#define PREP_BLOCKS ((EE + 255) / 256)        // 3125
#define G1_BLOCKS   ((NN + 63) / 64)          // 782
#define AGG1_BLOCKS ((NN / 4 * 32 + 255) / 256) // 1563 (4 nodes per warp)
#define AGG_BLOCKS  ((NN / 2 * 32 + 255) / 256) // 3125 (2 nodes per warp)
#define RST_BLOCKS  98                        // zero g_dc (2 ULL/thread) + g_lk
#define FILL_BLOCKS ((EE / 4 + 255) / 256)    // 782 (4 edges per thread)

#define DEG_SCALE 1048576.0f                  // 2^20 fixed point for edge-weight sums

// Scratch (device globals — no allocation allowed). Index 0/1 = tower.
__device__ unsigned long long g_dc[2][NN];    // hi32 = count, lo32 = fixedpoint sum(relu(w))
__device__ unsigned long long g_lk[2][64];    // lookback: hi32 flag (0/1/2), lo32 value
__device__ float  g_dinv[2][NN];
__device__ int    g_off [2][NN + 1];          // exclusive offsets (immutable after scan)
__device__ int    g_rank[2][EE];              // per-edge rank within its dst bucket
__device__ int2   g_edge[2][EE];              // (src, half2(norm,norm) bits)
__device__ __half g_h1h[2][NN * O1];          // layer-1 hidden fp16 (gather-bound)
__device__ float  g_z1 [2][NN * O1];
__device__ __half g_h2h[2][NN * O2];          // layer-2 hidden fp16 (gather-bound)

// ---------------------------------------------------------------------------
// packed fp32x2 FMA (sm_103a FFMA2)
// ---------------------------------------------------------------------------
__device__ __forceinline__ void ffma2(float2& acc, float2 a, float2 w) {
    unsigned long long ac, av, wv;
    ac = *(unsigned long long*)&acc;
    av = *(unsigned long long*)&a;
    wv = *(unsigned long long*)&w;
    asm("fma.rn.f32x2 %0, %1, %2, %0;" : "+l"(ac) : "l"(av), "l"(wv));
    acc = *(float2*)&ac;
}

// ---------------------------------------------------------------------------
// Register-tiled GEMM body: C[64-row tile, 64-col tile] = A[N,K] @ W[K,OC]
// 256 flat threads; each thread 4 rows x 4 cols; k paired for fma.rn.f32x2
// Output fp16
// ---------------------------------------------------------------------------
template<int K, int OC>
__device__ __forceinline__ void gemm_body(const float* __restrict__ A,
                                          const float* __restrict__ W,
                                          __half* __restrict__ C,
                                          int rowBlk, int colBase, int tid) {
    __shared__ float2 Wp[(K / 2) * 64];
    int tx = tid & 15;
    int ty = tid >> 4;
    for (int idx = tid; idx < (K / 2) * 64; idx += 256) {
        int kp = idx >> 6, c = idx & 63;
        Wp[idx] = make_float2(W[(2 * kp)     * OC + colBase + c],
                              W[(2 * kp + 1) * OC + colBase + c]);
    }
    __syncthreads();

    int r0 = rowBlk * 64 + ty * 4;
    int c0 = tx * 4;
    float2 acc[4][4];
#pragma unroll
    for (int i = 0; i < 4; i++)
#pragma unroll
        for (int j = 0; j < 4; j++) acc[i][j] = make_float2(0.0f, 0.0f);

#pragma unroll 4
    for (int kk = 0; kk < K; kk += 4) {
        float4 a[4];
#pragma unroll
        for (int i = 0; i < 4; i++) {
            int r = r0 + i;
            a[i] = (r < NN) ? *(const float4*)(A + (size_t)r * K + kk)
                            : make_float4(0.0f, 0.0f, 0.0f, 0.0f);
        }
#pragma unroll
        for (int kp = 0; kp < 2; kp++) {
            const float2* wrow = Wp + ((kk >> 1) + kp) * 64 + c0;
            float4 wA = *(const float4*)(wrow);
            float4 wB = *(const float4*)(wrow + 2);
            float2 w0 = make_float2(wA.x, wA.y);
            float2 w1 = make_float2(wA.z, wA.w);
            float2 w2 = make_float2(wB.x, wB.y);
            float2 w3 = make_float2(wB.z, wB.w);
#pragma unroll
            for (int i = 0; i < 4; i++) {
                float2 ap = kp ? make_float2(a[i].z, a[i].w)
                               : make_float2(a[i].x, a[i].y);
                ffma2(acc[i][0], ap, w0);
                ffma2(acc[i][1], ap, w1);
                ffma2(acc[i][2], ap, w2);
                ffma2(acc[i][3], ap, w3);
            }
        }
    }
#pragma unroll
    for (int i = 0; i < 4; i++) {
        int r = r0 + i;
        if (r < NN) {
            __half2 p0 = __floats2half2_rn(acc[i][0].x + acc[i][0].y,
                                           acc[i][1].x + acc[i][1].y);
            __half2 p1 = __floats2half2_rn(acc[i][2].x + acc[i][2].y,
                                           acc[i][3].x + acc[i][3].y);
            uint2 pk;
            pk.x = *(unsigned*)&p0;
            pk.y = *(unsigned*)&p1;
            *(uint2*)(C + (size_t)r * OC + colBase + c0) = pk;
        }
    }
}

// ---------------------------------------------------------------------------
// fused: packed deg/count atomics + rank capture | GEMM1
// ---------------------------------------------------------------------------
__global__ void k_prep_gemm1(const int* __restrict__ ei1, const float* __restrict__ ew1,
                             const int* __restrict__ ei2, const float* __restrict__ ew2,
                             const float* __restrict__ x1, const float* __restrict__ x2,
                             const float* __restrict__ W1) {
    int tw = blockIdx.y;
    if (blockIdx.x < PREP_BLOCKS) {
        const int*   ei = tw ? ei2 : ei1;
        const float* ew = tw ? ew2 : ew1;
        int e = blockIdx.x * 256 + threadIdx.x;
        if (e < EE) {
            int d = ei[EE + e];
            float w = fmaxf(ew[e], 0.0f);          // relu(edge_weight)
            unsigned long long pk =
                (1ULL << 32) | (unsigned long long)__float2uint_rn(w * DEG_SCALE);
            unsigned long long old = atomicAdd(&g_dc[tw][d], pk);
            g_rank[tw][e] = (int)(old >> 32);      // rank within dst bucket
        }
    } else {
        gemm_body<IN_DIM, O1>(tw ? x2 : x1, W1, g_h1h[tw],
                              blockIdx.x - PREP_BLOCKS, 0, threadIdx.x);
    }
}

// ---------------------------------------------------------------------------
// single-pass scan (decoupled lookback) + dinv. grid (NBLK,2) x 1024 threads
// ---------------------------------------------------------------------------
__global__ void k_scan() {
    int tw   = blockIdx.y;
    int b    = blockIdx.x;
    int i    = b * SCAN_B + threadIdx.x;
    int lane = threadIdx.x & 31;
    int wid  = threadIdx.x >> 5;
    unsigned long long dc = (i < NN) ? g_dc[tw][i] : 0ULL;
    int c = (int)(dc >> 32);
    int v = c;
#pragma unroll
    for (int d = 1; d < 32; d <<= 1) {
        int t = __shfl_up_sync(0xffffffffu, v, d);
        if (lane >= d) v += t;
    }
    __shared__ int wsum[32];
    if (lane == 31) wsum[wid] = v;
    __syncthreads();
    if (wid == 0) {
        int w = wsum[lane];
#pragma unroll
        for (int d = 1; d < 32; d <<= 1) {
            int t = __shfl_up_sync(0xffffffffu, w, d);
            if (lane >= d) w += t;
        }
        wsum[lane] = w;
    }
    __syncthreads();
    int add = (wid > 0) ? wsum[wid - 1] : 0;
    int incl = v + add;
    int total = wsum[31];

    __shared__ int s_exc;
    if (threadIdx.x == 0) {
        unsigned long long flag = (b == 0) ? 2ULL : 1ULL;
        atomicExch(&g_lk[tw][b], (flag << 32) | (unsigned)total);
        int exc = 0;
        if (b > 0) {
            int p = b - 1;
            while (true) {
                unsigned long long pv = *((volatile unsigned long long*)&g_lk[tw][p]);
                unsigned f = (unsigned)(pv >> 32);
                if (f == 2u) { exc += (int)(unsigned)pv; break; }
                if (f == 1u) { exc += (int)(unsigned)pv; p--; }
            }
            atomicExch(&g_lk[tw][b], (2ULL << 32) | (unsigned)(total + exc));
        }
        s_exc = exc;
    }
    __syncthreads();
    if (i < NN) {
        g_off[tw][i] = s_exc + incl - c;
        float deg = 2.0f + (float)(unsigned)dc * (1.0f / DEG_SCALE);
        g_dinv[tw][i] = rsqrtf(deg);
    }
    if (b == gridDim.x - 1 && threadIdx.x == 0) g_off[tw][NN] = EE;
}

// ---------------------------------------------------------------------------
// fill: atomic-free, 4 edges per thread (vectorized coalesced loads)
// ---------------------------------------------------------------------------
__global__ void k_fill(const int* __restrict__ ei1, const float* __restrict__ ew1,
                       const int* __restrict__ ei2, const float* __restrict__ ew2) {
    int tw = blockIdx.y;
    const int*   ei = tw ? ei2 : ei1;
    const float* ew = tw ? ew2 : ew1;
    int e0 = (blockIdx.x * 256 + threadIdx.x) * 4;
    if (e0 >= EE) return;
    int4   sv = *(const int4*)(ei + e0);
    int4   dv = *(const int4*)(ei + EE + e0);
    float4 wv = *(const float4*)(ew + e0);
    int4   rv = *(const int4*)(g_rank[tw] + e0);
    const float* dinv = g_dinv[tw];
    int2* edge = g_edge[tw];
    const int* off = g_off[tw];
    {
        float nrm = dinv[sv.x] * fmaxf(wv.x, 0.0f) * dinv[dv.x];
        __half2 nh = __float2half2_rn(nrm);
        edge[off[dv.x] + rv.x] = make_int2(sv.x, *(int*)&nh);
    }
    {
        float nrm = dinv[sv.y] * fmaxf(wv.y, 0.0f) * dinv[dv.y];
        __half2 nh = __float2half2_rn(nrm);
        edge[off[dv.y] + rv.y] = make_int2(sv.y, *(int*)&nh);
    }
    {
        float nrm = dinv[sv.z] * fmaxf(wv.z, 0.0f) * dinv[dv.z];
        __half2 nh = __float2half2_rn(nrm);
        edge[off[dv.z] + rv.z] = make_int2(sv.z, *(int*)&nh);
    }
    {
        float nrm = dinv[sv.w] * fmaxf(wv.w, 0.0f) * dinv[dv.w];
        __half2 nh = __float2half2_rn(nrm);
        edge[off[dv.w] + rv.w] = make_int2(sv.w, *(int*)&nh);
    }
}

__global__ void k_gemm2(const float* __restrict__ W2) {
    int tw = blockIdx.z;
    gemm_body<O1, O2>(g_z1[tw], W2, g_h2h[tw],
                      blockIdx.x, blockIdx.y * 64, threadIdx.y * 16 + threadIdx.x);
}

// ---------------------------------------------------------------------------
// Aggregation 1: 4 nodes per warp (8 lanes each, uint4 = 8 fp16 per lane)
// ---------------------------------------------------------------------------
__global__ void __launch_bounds__(256, 8)
k_aggr1(const float* __restrict__ b1) {
    int tw    = blockIdx.y;
    int gwarp = (blockIdx.x * blockDim.x + threadIdx.x) >> 5;
    int lane  = threadIdx.x & 31;
    int node  = gwarp * 4 + (lane >> 3);
    int ln    = lane & 7;
    if (node >= NN) return;
    const int2*   eg = g_edge[tw];
    const __half* h  = g_h1h[tw];
    int beg = g_off[tw][node];
    int end = g_off[tw][node + 1];
    float dv = g_dinv[tw][node];
    __half2 slh = __float2half2_rn(2.0f * dv * dv);
    uint4 selfpk = *(const uint4*)(h + (size_t)node * O1 + ln * 8);
    __half2 mA = __hmul2(*(__half2*)&selfpk.x, slh);
    __half2 mB = __hmul2(*(__half2*)&selfpk.y, slh);
    __half2 mC = __hmul2(*(__half2*)&selfpk.z, slh);
    __half2 mD = __hmul2(*(__half2*)&selfpk.w, slh);
    int j = beg;
    for (; j + 4 <= end; j += 4) {
        int2 e0 = eg[j], e1 = eg[j + 1], e2 = eg[j + 2], e3 = eg[j + 3];
        uint4 v0 = *(const uint4*)(h + (size_t)e0.x * O1 + ln * 8);
        uint4 v1 = *(const uint4*)(h + (size_t)e1.x * O1 + ln * 8);
        uint4 v2 = *(const uint4*)(h + (size_t)e2.x * O1 + ln * 8);
        uint4 v3 = *(const uint4*)(h + (size_t)e3.x * O1 + ln * 8);
        __half2 w0 = *(__half2*)&e0.y, w1 = *(__half2*)&e1.y;
        __half2 w2 = *(__half2*)&e2.y, w3 = *(__half2*)&e3.y;
        mA = __hmax2(mA, __hmul2(*(__half2*)&v0.x, w0));
        mB = __hmax2(mB, __hmul2(*(__half2*)&v0.y, w0));
        mC = __hmax2(mC, __hmul2(*(__half2*)&v0.z, w0));
        mD = __hmax2(mD, __hmul2(*(__half2*)&v0.w, w0));
        mA = __hmax2(mA, __hmul2(*(__half2*)&v1.x, w1));
        mB = __hmax2(mB, __hmul2(*(__half2*)&v1.y, w1));
        mC = __hmax2(mC, __hmul2(*(__half2*)&v1.z, w1));
        mD = __hmax2(mD, __hmul2(*(__half2*)&v1.w, w1));
        mA = __hmax2(mA, __hmul2(*(__half2*)&v2.x, w2));
        mB = __hmax2(mB, __hmul2(*(__half2*)&v2.y, w2));
        mC = __hmax2(mC, __hmul2(*(__half2*)&v2.z, w2));
        mD = __hmax2(mD, __hmul2(*(__half2*)&v2.w, w2));
        mA = __hmax2(mA, __hmul2(*(__half2*)&v3.x, w3));
        mB = __hmax2(mB, __hmul2(*(__half2*)&v3.y, w3));
        mC = __hmax2(mC, __hmul2(*(__half2*)&v3.z, w3));
        mD = __hmax2(mD, __hmul2(*(__half2*)&v3.w, w3));
    }
    for (; j < end; j++) {
        int2 e = eg[j];
        uint4 v = *(const uint4*)(h + (size_t)e.x * O1 + ln * 8);
        __half2 wh = *(__half2*)&e.y;
        mA = __hmax2(mA, __hmul2(*(__half2*)&v.x, wh));
        mB = __hmax2(mB, __hmul2(*(__half2*)&v.y, wh));
        mC = __hmax2(mC, __hmul2(*(__half2*)&v.z, wh));
        mD = __hmax2(mD, __hmul2(*(__half2*)&v.w, wh));
    }
    float2 fA = __half22float2(mA);
    float2 fB = __half22float2(mB);
    float2 fC = __half22float2(mC);
    float2 fD = __half22float2(mD);
    float m[8] = {fA.x, fA.y, fB.x, fB.y, fC.x, fC.y, fD.x, fD.y};
#pragma unroll
    for (int q = 0; q < 8; q++)
        if (!isfinite(m[q])) m[q] = 0.0f;
    float4 bv0 = *(const float4*)(b1 + ln * 8);
    float4 bv1 = *(const float4*)(b1 + ln * 8 + 4);
    float* dst = g_z1[tw] + (size_t)node * O1 + ln * 8;
    *(float4*)(dst)     = make_float4(m[0] + bv0.x, m[1] + bv0.y, m[2] + bv0.z, m[3] + bv0.w);
    *(float4*)(dst + 4) = make_float4(m[4] + bv1.x, m[5] + bv1.y, m[6] + bv1.z, m[7] + bv1.w);
}

// ---------------------------------------------------------------------------
// Aggregation 2: 2 nodes per warp (16 lanes each, uint4 = 8 fp16 per lane);
// tail blocks reset g_dc / g_lk for the next invocation
// ---------------------------------------------------------------------------
__device__ __forceinline__ void max8_half(__half2& mA, __half2& mB, __half2& mC, __half2& mD,
                                          uint4 pk, __half2 wh) {
    mA = __hmax2(mA, __hmul2(*(__half2*)&pk.x, wh));
    mB = __hmax2(mB, __hmul2(*(__half2*)&pk.y, wh));
    mC = __hmax2(mC, __hmul2(*(__half2*)&pk.z, wh));
    mD = __hmax2(mD, __hmul2(*(__half2*)&pk.w, wh));
}

__global__ void __launch_bounds__(256, 8)
k_aggr2(const float* __restrict__ b2, float* __restrict__ out) {
    int tw = blockIdx.y;
    if (blockIdx.x >= AGG_BLOCKS) {
        int rb  = blockIdx.x - AGG_BLOCKS;
        int idx = (rb * 256 + threadIdx.x) * 2;
        if (idx     < NN) g_dc[tw][idx]     = 0ULL;
        if (idx + 1 < NN) g_dc[tw][idx + 1] = 0ULL;
        if (rb == 0 && threadIdx.x < 64) g_lk[tw][threadIdx.x] = 0ULL;
        return;
    }
    int gwarp = (blockIdx.x * blockDim.x + threadIdx.x) >> 5;
    int lane  = threadIdx.x & 31;
    int node  = gwarp * 2 + (lane >> 4);
    int ln    = lane & 15;
    if (node >= NN) return;
    const int2*   eg = g_edge[tw];
    const __half* h  = g_h2h[tw];
    float* op = out + (size_t)tw * NN * O2;
    int beg = g_off[tw][node];
    int end = g_off[tw][node + 1];
    float dv = g_dinv[tw][node];
    __half2 slh = __float2half2_rn(2.0f * dv * dv);
    uint4 selfpk = *(const uint4*)(h + (size_t)node * O2 + ln * 8);
    __half2 mA = __hmul2(*(__half2*)&selfpk.x, slh);
    __half2 mB = __hmul2(*(__half2*)&selfpk.y, slh);
    __half2 mC = __hmul2(*(__half2*)&selfpk.z, slh);
    __half2 mD = __hmul2(*(__half2*)&selfpk.w, slh);
    int j = beg;
    for (; j + 4 <= end; j += 4) {
        int2 e0 = eg[j], e1 = eg[j + 1], e2 = eg[j + 2], e3 = eg[j + 3];
        uint4 v0 = *(const uint4*)(h + (size_t)e0.x * O2 + ln * 8);
        uint4 v1 = *(const uint4*)(h + (size_t)e1.x * O2 + ln * 8);
        uint4 v2 = *(const uint4*)(h + (size_t)e2.x * O2 + ln * 8);
        uint4 v3 = *(const uint4*)(h + (size_t)e3.x * O2 + ln * 8);
        max8_half(mA, mB, mC, mD, v0, *(__half2*)&e0.y);
        max8_half(mA, mB, mC, mD, v1, *(__half2*)&e1.y);
        max8_half(mA, mB, mC, mD, v2, *(__half2*)&e2.y);
        max8_half(mA, mB, mC, mD, v3, *(__half2*)&e3.y);
    }
    for (; j < end; j++) {
        int2 e = eg[j];
        uint4 v = *(const uint4*)(h + (size_t)e.x * O2 + ln * 8);
        max8_half(mA, mB, mC, mD, v, *(__half2*)&e.y);
    }
    float2 fA = __half22float2(mA);
    float2 fB = __half22float2(mB);
    float2 fC = __half22float2(mC);
    float2 fD = __half22float2(mD);
    float m[8] = {fA.x, fA.y, fB.x, fB.y, fC.x, fC.y, fD.x, fD.y};
#pragma unroll
    for (int q = 0; q < 8; q++)
        if (!isfinite(m[q])) m[q] = 0.0f;
    float4 bv0 = *(const float4*)(b2 + ln * 8);
    float4 bv1 = *(const float4*)(b2 + ln * 8 + 4);
    float* dst = op + (size_t)node * O2 + ln * 8;
    *(float4*)(dst)     = make_float4(m[0] + bv0.x, m[1] + bv0.y, m[2] + bv0.z, m[3] + bv0.w);
    *(float4*)(dst + 4) = make_float4(m[4] + bv1.x, m[5] + bv1.y, m[6] + bv1.z, m[7] + bv1.w);
}

// ---------------------------------------------------------------------------
// launch
// ---------------------------------------------------------------------------
extern "C" void kernel_launch(void* const* d_in, const int* in_sizes, int n_in,
                              void* d_out, int out_size) {
    const float* x1  = (const float*)d_in[0];
    const int*   ei1 = (const int*)  d_in[1];
    const float* ew1 = (const float*)d_in[2];
    const float* x2  = (const float*)d_in[3];
    const int*   ei2 = (const int*)  d_in[4];
    const float* ew2 = (const float*)d_in[5];
    const float* W1  = (const float*)d_in[6];
    const float* b1  = (const float*)d_in[7];
    const float* W2  = (const float*)d_in[8];
    const float* b2  = (const float*)d_in[9];
    float* out = (float*)d_out;

    const int TB = 256;
    k_prep_gemm1<<<dim3(PREP_BLOCKS + G1_BLOCKS, 2), TB>>>(ei1, ew1, ei2, ew2, x1, x2, W1);
    k_scan      <<<dim3(NBLK, 2), SCAN_B>>>();
    k_fill      <<<dim3(FILL_BLOCKS, 2), TB>>>(ei1, ew1, ei2, ew2);

    k_aggr1<<<dim3(AGG1_BLOCKS, 2), TB>>>(b1);
    dim3 gblk(16, 16);
    k_gemm2<<<dim3(G1_BLOCKS, 2, 2), gblk>>>(W2);
    k_aggr2<<<dim3(AGG_BLOCKS + RST_BLOCKS, 2), TB>>>(b2, out);
}

// round 16
// speedup vs baseline: 1.0549x; 1.0010x over previous
#include <cuda_runtime.h>
#include <cuda_fp16.h>
#include <math.h>

#define NN   50000
#define EE   800000
#define IN_DIM 128
#define O1   64
#define O2   128

#define SCAN_B 1024
#define NBLK   ((NN + SCAN_B - 1) / SCAN_B)   // 49

#define PREP_BLOCKS ((EE + 255) / 256)        // 3125
#define G1_BLOCKS   ((NN + 63) / 64)          // 782
#define AGG1_BLOCKS ((NN / 4 * 32 + 255) / 256) // 1563 (4 nodes per warp)
#define AGG_BLOCKS  ((NN / 2 * 32 + 255) / 256) // 3125 (2 nodes per warp)
#define RST_BLOCKS  98                        // zero g_dc (2 ULL/thread) + g_lk
#define FILL_BLOCKS ((EE / 4 + 255) / 256)    // 782 (4 edges per thread)

#define DEG_SCALE 1048576.0f                  // 2^20 fixed point for edge-weight sums

// Scratch (device globals — no allocation allowed). Index 0/1 = tower.
__device__ unsigned long long g_dc[2][NN];    // hi32 = count, lo32 = fixedpoint sum(relu(w))
__device__ unsigned long long g_lk[2][64];    // lookback: hi32 flag (0/1/2), lo32 value
__device__ float  g_dinv[2][NN];
__device__ int    g_off [2][NN + 1];          // exclusive offsets (immutable after scan)
__device__ int    g_rank[2][EE];              // per-edge rank within its dst bucket
__device__ __align__(16) int2 g_edge[2][EE];  // (src, half2(norm,norm) bits), 16B-aligned
__device__ __half g_h1h[2][NN * O1];          // layer-1 hidden fp16 (gather-bound)
__device__ float  g_z1 [2][NN * O1];
__device__ __half g_h2h[2][NN * O2];          // layer-2 hidden fp16 (gather-bound)

// ---------------------------------------------------------------------------
// packed fp32x2 FMA (sm_103a FFMA2)
// ---------------------------------------------------------------------------
__device__ __forceinline__ void ffma2(float2& acc, float2 a, float2 w) {
    unsigned long long ac, av, wv;
    ac = *(unsigned long long*)&acc;
    av = *(unsigned long long*)&a;
    wv = *(unsigned long long*)&w;
    asm("fma.rn.f32x2 %0, %1, %2, %0;" : "+l"(ac) : "l"(av), "l"(wv));
    acc = *(float2*)&ac;
}

// ---------------------------------------------------------------------------
// Register-tiled GEMM body: C[64-row tile, 64-col tile] = A[N,K] @ W[K,OC]
// ---------------------------------------------------------------------------
template<int K, int OC>
__device__ __forceinline__ void gemm_body(const float* __restrict__ A,
                                          const float* __restrict__ W,
                                          __half* __restrict__ C,
                                          int rowBlk, int colBase, int tid) {
    __shared__ float2 Wp[(K / 2) * 64];
    int tx = tid & 15;
    int ty = tid >> 4;
    for (int idx = tid; idx < (K / 2) * 64; idx += 256) {
        int kp = idx >> 6, c = idx & 63;
        Wp[idx] = make_float2(W[(2 * kp)     * OC + colBase + c],
                              W[(2 * kp + 1) * OC + colBase + c]);
    }
    __syncthreads();

    int r0 = rowBlk * 64 + ty * 4;
    int c0 = tx * 4;
    float2 acc[4][4];
#pragma unroll
    for (int i = 0; i < 4; i++)
#pragma unroll
        for (int j = 0; j < 4; j++) acc[i][j] = make_float2(0.0f, 0.0f);

#pragma unroll 4
    for (int kk = 0; kk < K; kk += 4) {
        float4 a[4];
#pragma unroll
        for (int i = 0; i < 4; i++) {
            int r = r0 + i;
            a[i] = (r < NN) ? *(const float4*)(A + (size_t)r * K + kk)
                            : make_float4(0.0f, 0.0f, 0.0f, 0.0f);
        }
#pragma unroll
        for (int kp = 0; kp < 2; kp++) {
            const float2* wrow = Wp + ((kk >> 1) + kp) * 64 + c0;
            float4 wA = *(const float4*)(wrow);
            float4 wB = *(const float4*)(wrow + 2);
            float2 w0 = make_float2(wA.x, wA.y);
            float2 w1 = make_float2(wA.z, wA.w);
            float2 w2 = make_float2(wB.x, wB.y);
            float2 w3 = make_float2(wB.z, wB.w);
#pragma unroll
            for (int i = 0; i < 4; i++) {
                float2 ap = kp ? make_float2(a[i].z, a[i].w)
                               : make_float2(a[i].x, a[i].y);
                ffma2(acc[i][0], ap, w0);
                ffma2(acc[i][1], ap, w1);
                ffma2(acc[i][2], ap, w2);
                ffma2(acc[i][3], ap, w3);
            }
        }
    }
#pragma unroll
    for (int i = 0; i < 4; i++) {
        int r = r0 + i;
        if (r < NN) {
            __half2 p0 = __floats2half2_rn(acc[i][0].x + acc[i][0].y,
                                           acc[i][1].x + acc[i][1].y);
            __half2 p1 = __floats2half2_rn(acc[i][2].x + acc[i][2].y,
                                           acc[i][3].x + acc[i][3].y);
            uint2 pk;
            pk.x = *(unsigned*)&p0;
            pk.y = *(unsigned*)&p1;
            *(uint2*)(C + (size_t)r * OC + colBase + c0) = pk;
        }
    }
}

// ---------------------------------------------------------------------------
// fused: packed deg/count atomics + rank capture | GEMM1
// ---------------------------------------------------------------------------
__global__ void k_prep_gemm1(const int* __restrict__ ei1, const float* __restrict__ ew1,
                             const int* __restrict__ ei2, const float* __restrict__ ew2,
                             const float* __restrict__ x1, const float* __restrict__ x2,
                             const float* __restrict__ W1) {
    int tw = blockIdx.y;
    if (blockIdx.x < PREP_BLOCKS) {
        const int*   ei = tw ? ei2 : ei1;
        const float* ew = tw ? ew2 : ew1;
        int e = blockIdx.x * 256 + threadIdx.x;
        if (e < EE) {
            int d = ei[EE + e];
            float w = fmaxf(ew[e], 0.0f);          // relu(edge_weight)
            unsigned long long pk =
                (1ULL << 32) | (unsigned long long)__float2uint_rn(w * DEG_SCALE);
            unsigned long long old = atomicAdd(&g_dc[tw][d], pk);
            g_rank[tw][e] = (int)(old >> 32);      // rank within dst bucket
        }
    } else {
        gemm_body<IN_DIM, O1>(tw ? x2 : x1, W1, g_h1h[tw],
                              blockIdx.x - PREP_BLOCKS, 0, threadIdx.x);
    }
}

// ---------------------------------------------------------------------------
// single-pass scan (decoupled lookback) + dinv. grid (NBLK,2) x 1024 threads
// ---------------------------------------------------------------------------
__global__ void k_scan() {
    int tw   = blockIdx.y;
    int b    = blockIdx.x;
    int i    = b * SCAN_B + threadIdx.x;
    int lane = threadIdx.x & 31;
    int wid  = threadIdx.x >> 5;
    unsigned long long dc = (i < NN) ? g_dc[tw][i] : 0ULL;
    int c = (int)(dc >> 32);
    int v = c;
#pragma unroll
    for (int d = 1; d < 32; d <<= 1) {
        int t = __shfl_up_sync(0xffffffffu, v, d);
        if (lane >= d) v += t;
    }
    __shared__ int wsum[32];
    if (lane == 31) wsum[wid] = v;
    __syncthreads();
    if (wid == 0) {
        int w = wsum[lane];
#pragma unroll
        for (int d = 1; d < 32; d <<= 1) {
            int t = __shfl_up_sync(0xffffffffu, w, d);
            if (lane >= d) w += t;
        }
        wsum[lane] = w;
    }
    __syncthreads();
    int add = (wid > 0) ? wsum[wid - 1] : 0;
    int incl = v + add;
    int total = wsum[31];

    __shared__ int s_exc;
    if (threadIdx.x == 0) {
        unsigned long long flag = (b == 0) ? 2ULL : 1ULL;
        atomicExch(&g_lk[tw][b], (flag << 32) | (unsigned)total);
        int exc = 0;
        if (b > 0) {
            int p = b - 1;
            while (true) {
                unsigned long long pv = *((volatile unsigned long long*)&g_lk[tw][p]);
                unsigned f = (unsigned)(pv >> 32);
                if (f == 2u) { exc += (int)(unsigned)pv; break; }
                if (f == 1u) { exc += (int)(unsigned)pv; p--; }
            }
            atomicExch(&g_lk[tw][b], (2ULL << 32) | (unsigned)(total + exc));
        }
        s_exc = exc;
    }
    __syncthreads();
    if (i < NN) {
        g_off[tw][i] = s_exc + incl - c;
        float deg = 2.0f + (float)(unsigned)dc * (1.0f / DEG_SCALE);
        g_dinv[tw][i] = rsqrtf(deg);
    }
    if (b == gridDim.x - 1 && threadIdx.x == 0) g_off[tw][NN] = EE;
}

// ---------------------------------------------------------------------------
// fill: atomic-free, 4 edges per thread (vectorized coalesced loads)
// ---------------------------------------------------------------------------
__global__ void k_fill(const int* __restrict__ ei1, const float* __restrict__ ew1,
                       const int* __restrict__ ei2, const float* __restrict__ ew2) {
    int tw = blockIdx.y;
    const int*   ei = tw ? ei2 : ei1;
    const float* ew = tw ? ew2 : ew1;
    int e0 = (blockIdx.x * 256 + threadIdx.x) * 4;
    if (e0 >= EE) return;
    int4   sv = *(const int4*)(ei + e0);
    int4   dv = *(const int4*)(ei + EE + e0);
    float4 wv = *(const float4*)(ew + e0);
    int4   rv = *(const int4*)(g_rank[tw] + e0);
    const float* dinv = g_dinv[tw];
    int2* edge = g_edge[tw];
    const int* off = g_off[tw];
    {
        float nrm = dinv[sv.x] * fmaxf(wv.x, 0.0f) * dinv[dv.x];
        __half2 nh = __float2half2_rn(nrm);
        edge[off[dv.x] + rv.x] = make_int2(sv.x, *(int*)&nh);
    }
    {
        float nrm = dinv[sv.y] * fmaxf(wv.y, 0.0f) * dinv[dv.y];
        __half2 nh = __float2half2_rn(nrm);
        edge[off[dv.y] + rv.y] = make_int2(sv.y, *(int*)&nh);
    }
    {
        float nrm = dinv[sv.z] * fmaxf(wv.z, 0.0f) * dinv[dv.z];
        __half2 nh = __float2half2_rn(nrm);
        edge[off[dv.z] + rv.z] = make_int2(sv.z, *(int*)&nh);
    }
    {
        float nrm = dinv[sv.w] * fmaxf(wv.w, 0.0f) * dinv[dv.w];
        __half2 nh = __float2half2_rn(nrm);
        edge[off[dv.w] + rv.w] = make_int2(sv.w, *(int*)&nh);
    }
}

__global__ void k_gemm2(const float* __restrict__ W2) {
    int tw = blockIdx.z;
    gemm_body<O1, O2>(g_z1[tw], W2, g_h2h[tw],
                      blockIdx.x, blockIdx.y * 64, threadIdx.y * 16 + threadIdx.x);
}

// ---------------------------------------------------------------------------
// Aggregation 1: 4 nodes per warp (8 lanes each, uint4 = 8 fp16 per lane);
// edge records fetched 4-at-a-time via two 16B loads (alignment prologue)
// ---------------------------------------------------------------------------
__device__ __forceinline__ void agg1_edge(__half2& mA, __half2& mB, __half2& mC, __half2& mD,
                                          const __half* __restrict__ h, int src, int nbits,
                                          int ln) {
    uint4 v = *(const uint4*)(h + (size_t)src * O1 + ln * 8);
    __half2 wh = *(__half2*)&nbits;
    mA = __hmax2(mA, __hmul2(*(__half2*)&v.x, wh));
    mB = __hmax2(mB, __hmul2(*(__half2*)&v.y, wh));
    mC = __hmax2(mC, __hmul2(*(__half2*)&v.z, wh));
    mD = __hmax2(mD, __hmul2(*(__half2*)&v.w, wh));
}

__global__ void __launch_bounds__(256, 8)
k_aggr1(const float* __restrict__ b1) {
    int tw    = blockIdx.y;
    int gwarp = (blockIdx.x * blockDim.x + threadIdx.x) >> 5;
    int lane  = threadIdx.x & 31;
    int node  = gwarp * 4 + (lane >> 3);
    int ln    = lane & 7;
    if (node >= NN) return;
    const int2*   eg = g_edge[tw];
    const __half* h  = g_h1h[tw];
    int beg = g_off[tw][node];
    int end = g_off[tw][node + 1];
    float dv = g_dinv[tw][node];
    __half2 slh = __float2half2_rn(2.0f * dv * dv);
    uint4 selfpk = *(const uint4*)(h + (size_t)node * O1 + ln * 8);
    __half2 mA = __hmul2(*(__half2*)&selfpk.x, slh);
    __half2 mB = __hmul2(*(__half2*)&selfpk.y, slh);
    __half2 mC = __hmul2(*(__half2*)&selfpk.z, slh);
    __half2 mD = __hmul2(*(__half2*)&selfpk.w, slh);
    int j = beg;
    if (j < end && (j & 1)) {                 // align to 16B record boundary
        int2 e = eg[j++];
        agg1_edge(mA, mB, mC, mD, h, e.x, e.y, ln);
    }
    for (; j + 4 <= end; j += 4) {
        uint4 ra = *(const uint4*)(eg + j);       // records j, j+1
        uint4 rb = *(const uint4*)(eg + j + 2);   // records j+2, j+3
        agg1_edge(mA, mB, mC, mD, h, (int)ra.x, (int)ra.y, ln);
        agg1_edge(mA, mB, mC, mD, h, (int)ra.z, (int)ra.w, ln);
        agg1_edge(mA, mB, mC, mD, h, (int)rb.x, (int)rb.y, ln);
        agg1_edge(mA, mB, mC, mD, h, (int)rb.z, (int)rb.w, ln);
    }
    for (; j < end; j++) {
        int2 e = eg[j];
        agg1_edge(mA, mB, mC, mD, h, e.x, e.y, ln);
    }
    float2 fA = __half22float2(mA);
    float2 fB = __half22float2(mB);
    float2 fC = __half22float2(mC);
    float2 fD = __half22float2(mD);
    float m[8] = {fA.x, fA.y, fB.x, fB.y, fC.x, fC.y, fD.x, fD.y};
#pragma unroll
    for (int q = 0; q < 8; q++)
        if (!isfinite(m[q])) m[q] = 0.0f;
    float4 bv0 = *(const float4*)(b1 + ln * 8);
    float4 bv1 = *(const float4*)(b1 + ln * 8 + 4);
    float* dst = g_z1[tw] + (size_t)node * O1 + ln * 8;
    *(float4*)(dst)     = make_float4(m[0] + bv0.x, m[1] + bv0.y, m[2] + bv0.z, m[3] + bv0.w);
    *(float4*)(dst + 4) = make_float4(m[4] + bv1.x, m[5] + bv1.y, m[6] + bv1.z, m[7] + bv1.w);
}

// ---------------------------------------------------------------------------
// Aggregation 2: 2 nodes per warp (16 lanes each, uint4 = 8 fp16 per lane);
// vectorized record fetch; tail blocks reset g_dc / g_lk for next invocation
// ---------------------------------------------------------------------------
__device__ __forceinline__ void agg2_edge(__half2& mA, __half2& mB, __half2& mC, __half2& mD,
                                          const __half* __restrict__ h, int src, int nbits,
                                          int ln) {
    uint4 v = *(const uint4*)(h + (size_t)src * O2 + ln * 8);
    __half2 wh = *(__half2*)&nbits;
    mA = __hmax2(mA, __hmul2(*(__half2*)&v.x, wh));
    mB = __hmax2(mB, __hmul2(*(__half2*)&v.y, wh));
    mC = __hmax2(mC, __hmul2(*(__half2*)&v.z, wh));
    mD = __hmax2(mD, __hmul2(*(__half2*)&v.w, wh));
}

__global__ void __launch_bounds__(256, 8)
k_aggr2(const float* __restrict__ b2, float* __restrict__ out) {
    int tw = blockIdx.y;
    if (blockIdx.x >= AGG_BLOCKS) {
        int rb  = blockIdx.x - AGG_BLOCKS;
        int idx = (rb * 256 + threadIdx.x) * 2;
        if (idx     < NN) g_dc[tw][idx]     = 0ULL;
        if (idx + 1 < NN) g_dc[tw][idx + 1] = 0ULL;
        if (rb == 0 && threadIdx.x < 64) g_lk[tw][threadIdx.x] = 0ULL;
        return;
    }
    int gwarp = (blockIdx.x * blockDim.x + threadIdx.x) >> 5;
    int lane  = threadIdx.x & 31;
    int node  = gwarp * 2 + (lane >> 4);
    int ln    = lane & 15;
    if (node >= NN) return;
    const int2*   eg = g_edge[tw];
    const __half* h  = g_h2h[tw];
    float* op = out + (size_t)tw * NN * O2;
    int beg = g_off[tw][node];
    int end = g_off[tw][node + 1];
    float dv = g_dinv[tw][node];
    __half2 slh = __float2half2_rn(2.0f * dv * dv);
    uint4 selfpk = *(const uint4*)(h + (size_t)node * O2 + ln * 8);
    __half2 mA = __hmul2(*(__half2*)&selfpk.x, slh);
    __half2 mB = __hmul2(*(__half2*)&selfpk.y, slh);
    __half2 mC = __hmul2(*(__half2*)&selfpk.z, slh);
    __half2 mD = __hmul2(*(__half2*)&selfpk.w, slh);
    int j = beg;
    if (j < end && (j & 1)) {                 // align to 16B record boundary
        int2 e = eg[j++];
        agg2_edge(mA, mB, mC, mD, h, e.x, e.y, ln);
    }
    for (; j + 4 <= end; j += 4) {
        uint4 ra = *(const uint4*)(eg + j);
        uint4 rb = *(const uint4*)(eg + j + 2);
        agg2_edge(mA, mB, mC, mD, h, (int)ra.x, (int)ra.y, ln);
        agg2_edge(mA, mB, mC, mD, h, (int)ra.z, (int)ra.w, ln);
        agg2_edge(mA, mB, mC, mD, h, (int)rb.x, (int)rb.y, ln);
        agg2_edge(mA, mB, mC, mD, h, (int)rb.z, (int)rb.w, ln);
    }
    for (; j < end; j++) {
        int2 e = eg[j];
        agg2_edge(mA, mB, mC, mD, h, e.x, e.y, ln);
    }
    float2 fA = __half22float2(mA);
    float2 fB = __half22float2(mB);
    float2 fC = __half22float2(mC);
    float2 fD = __half22float2(mD);
    float m[8] = {fA.x, fA.y, fB.x, fB.y, fC.x, fC.y, fD.x, fD.y};
#pragma unroll
    for (int q = 0; q < 8; q++)
        if (!isfinite(m[q])) m[q] = 0.0f;
    float4 bv0 = *(const float4*)(b2 + ln * 8);
    float4 bv1 = *(const float4*)(b2 + ln * 8 + 4);
    float* dst = op + (size_t)node * O2 + ln * 8;
    *(float4*)(dst)     = make_float4(m[0] + bv0.x, m[1] + bv0.y, m[2] + bv0.z, m[3] + bv0.w);
    *(float4*)(dst + 4) = make_float4(m[4] + bv1.x, m[5] + bv1.y, m[6] + bv1.z, m[7] + bv1.w);
}

// ---------------------------------------------------------------------------
// launch
// ---------------------------------------------------------------------------
extern "C" void kernel_launch(void* const* d_in, const int* in_sizes, int n_in,
                              void* d_out, int out_size) {
    const float* x1  = (const float*)d_in[0];
    const int*   ei1 = (const int*)  d_in[1];
    const float* ew1 = (const float*)d_in[2];
    const float* x2  = (const float*)d_in[3];
    const int*   ei2 = (const int*)  d_in[4];
    const float* ew2 = (const float*)d_in[5];
    const float* W1  = (const float*)d_in[6];
    const float* b1  = (const float*)d_in[7];
    const float* W2  = (const float*)d_in[8];
    const float* b2  = (const float*)d_in[9];
    float* out = (float*)d_out;

    const int TB = 256;
    k_prep_gemm1<<<dim3(PREP_BLOCKS + G1_BLOCKS, 2), TB>>>(ei1, ew1, ei2, ew2, x1, x2, W1);
    k_scan      <<<dim3(NBLK, 2), SCAN_B>>>();
    k_fill      <<<dim3(FILL_BLOCKS, 2), TB>>>(ei1, ew1, ei2, ew2);

    k_aggr1<<<dim3(AGG1_BLOCKS, 2), TB>>>(b1);
    dim3 gblk(16, 16);
    k_gemm2<<<dim3(G1_BLOCKS, 2, 2), gblk>>>(W2);
    k_aggr2<<<dim3(AGG_BLOCKS + RST_BLOCKS, 2), TB>>>(b2, out);
}

// round 17
// speedup vs baseline: 1.0895x; 1.0329x over previous
#include <cuda_runtime.h>
#include <cuda_fp16.h>
#include <math.h>

#define NN   50000
#define EE   800000
#define IN_DIM 128
#define O1   64
#define O2   128

#define SCAN_B 1024
#define NBLK   ((NN + SCAN_B - 1) / SCAN_B)   // 49

#define PREP_BLOCKS ((EE + 255) / 256)        // 3125
#define G1_BLOCKS   ((NN + 63) / 64)          // 782
#define AGG1_BLOCKS ((NN / 4 * 32 + 255) / 256) // 1563 (4 nodes per warp)
#define AGG_BLOCKS  ((NN / 2 * 32 + 255) / 256) // 3125 (2 nodes per warp)
#define RST_BLOCKS  98                        // zero g_dc (2 ULL/thread) + g_lk
#define FILL_BLOCKS ((EE / 4 + 255) / 256)    // 782 (4 edges per thread)

#define DEG_SCALE 1048576.0f                  // 2^20 fixed point for edge-weight sums

// Scratch (device globals — no allocation allowed). Index 0/1 = tower.
__device__ unsigned long long g_dc[2][NN];    // hi32 = count, lo32 = fixedpoint sum(relu(w))
__device__ unsigned long long g_lk[2][64];    // lookback: hi32 flag (0/1/2), lo32 value
__device__ float  g_dinv[2][NN];
__device__ int    g_off [2][NN + 1];          // exclusive offsets (immutable after scan)
__device__ int    g_rank[2][EE];              // per-edge rank within its dst bucket
__device__ __align__(16) int2 g_edge[2][EE];  // (src, half2(norm,norm) bits)
__device__ __half g_h1h[2][NN * O1];          // layer-1 hidden fp16 (gather-bound)
__device__ float  g_z1 [2][NN * O1];
__device__ __half g_h2h[2][NN * O2];          // layer-2 hidden fp16 (gather-bound)

// ---------------------------------------------------------------------------
// packed fp32x2 FMA (sm_103a FFMA2)
// ---------------------------------------------------------------------------
__device__ __forceinline__ void ffma2(float2& acc, float2 a, float2 w) {
    unsigned long long ac, av, wv;
    ac = *(unsigned long long*)&acc;
    av = *(unsigned long long*)&a;
    wv = *(unsigned long long*)&w;
    asm("fma.rn.f32x2 %0, %1, %2, %0;" : "+l"(ac) : "l"(av), "l"(wv));
    acc = *(float2*)&ac;
}

// ---------------------------------------------------------------------------
// Register-tiled GEMM body: C[64-row tile, 64-col tile] = A[N,K] @ W[K,OC]
// ---------------------------------------------------------------------------
template<int K, int OC>
__device__ __forceinline__ void gemm_body(const float* __restrict__ A,
                                          const float* __restrict__ W,
                                          __half* __restrict__ C,
                                          int rowBlk, int colBase, int tid) {
    __shared__ float2 Wp[(K / 2) * 64];
    int tx = tid & 15;
    int ty = tid >> 4;
    for (int idx = tid; idx < (K / 2) * 64; idx += 256) {
        int kp = idx >> 6, c = idx & 63;
        Wp[idx] = make_float2(W[(2 * kp)     * OC + colBase + c],
                              W[(2 * kp + 1) * OC + colBase + c]);
    }
    __syncthreads();

    int r0 = rowBlk * 64 + ty * 4;
    int c0 = tx * 4;
    float2 acc[4][4];
#pragma unroll
    for (int i = 0; i < 4; i++)
#pragma unroll
        for (int j = 0; j < 4; j++) acc[i][j] = make_float2(0.0f, 0.0f);

#pragma unroll 4
    for (int kk = 0; kk < K; kk += 4) {
        float4 a[4];
#pragma unroll
        for (int i = 0; i < 4; i++) {
            int r = r0 + i;
            a[i] = (r < NN) ? *(const float4*)(A + (size_t)r * K + kk)
                            : make_float4(0.0f, 0.0f, 0.0f, 0.0f);
        }
#pragma unroll
        for (int kp = 0; kp < 2; kp++) {
            const float2* wrow = Wp + ((kk >> 1) + kp) * 64 + c0;
            float4 wA = *(const float4*)(wrow);
            float4 wB = *(const float4*)(wrow + 2);
            float2 w0 = make_float2(wA.x, wA.y);
            float2 w1 = make_float2(wA.z, wA.w);
            float2 w2 = make_float2(wB.x, wB.y);
            float2 w3 = make_float2(wB.z, wB.w);
#pragma unroll
            for (int i = 0; i < 4; i++) {
                float2 ap = kp ? make_float2(a[i].z, a[i].w)
                               : make_float2(a[i].x, a[i].y);
                ffma2(acc[i][0], ap, w0);
                ffma2(acc[i][1], ap, w1);
                ffma2(acc[i][2], ap, w2);
                ffma2(acc[i][3], ap, w3);
            }
        }
    }
#pragma unroll
    for (int i = 0; i < 4; i++) {
        int r = r0 + i;
        if (r < NN) {
            __half2 p0 = __floats2half2_rn(acc[i][0].x + acc[i][0].y,
                                           acc[i][1].x + acc[i][1].y);
            __half2 p1 = __floats2half2_rn(acc[i][2].x + acc[i][2].y,
                                           acc[i][3].x + acc[i][3].y);
            uint2 pk;
            pk.x = *(unsigned*)&p0;
            pk.y = *(unsigned*)&p1;
            *(uint2*)(C + (size_t)r * OC + colBase + c0) = pk;
        }
    }
}

// ---------------------------------------------------------------------------
// fused: GEMM1 first (long blocks get wave-1 slots), then deg/count atomics
// ---------------------------------------------------------------------------
__global__ void k_prep_gemm1(const int* __restrict__ ei1, const float* __restrict__ ew1,
                             const int* __restrict__ ei2, const float* __restrict__ ew2,
                             const float* __restrict__ x1, const float* __restrict__ x2,
                             const float* __restrict__ W1) {
    int tw = blockIdx.y;
    if (blockIdx.x < G1_BLOCKS) {
        gemm_body<IN_DIM, O1>(tw ? x2 : x1, W1, g_h1h[tw], blockIdx.x, 0, threadIdx.x);
    } else {
        const int*   ei = tw ? ei2 : ei1;
        const float* ew = tw ? ew2 : ew1;
        int e = (blockIdx.x - G1_BLOCKS) * 256 + threadIdx.x;
        if (e < EE) {
            int d = ei[EE + e];
            float w = fmaxf(ew[e], 0.0f);          // relu(edge_weight)
            unsigned long long pk =
                (1ULL << 32) | (unsigned long long)__float2uint_rn(w * DEG_SCALE);
            unsigned long long old = atomicAdd(&g_dc[tw][d], pk);
            g_rank[tw][e] = (int)(old >> 32);      // rank within dst bucket
        }
    }
}

// ---------------------------------------------------------------------------
// single-pass scan (decoupled lookback) + dinv. grid (NBLK,2) x 1024 threads
// ---------------------------------------------------------------------------
__global__ void k_scan() {
    int tw   = blockIdx.y;
    int b    = blockIdx.x;
    int i    = b * SCAN_B + threadIdx.x;
    int lane = threadIdx.x & 31;
    int wid  = threadIdx.x >> 5;
    unsigned long long dc = (i < NN) ? g_dc[tw][i] : 0ULL;
    int c = (int)(dc >> 32);
    int v = c;
#pragma unroll
    for (int d = 1; d < 32; d <<= 1) {
        int t = __shfl_up_sync(0xffffffffu, v, d);
        if (lane >= d) v += t;
    }
    __shared__ int wsum[32];
    if (lane == 31) wsum[wid] = v;
    __syncthreads();
    if (wid == 0) {
        int w = wsum[lane];
#pragma unroll
        for (int d = 1; d < 32; d <<= 1) {
            int t = __shfl_up_sync(0xffffffffu, w, d);
            if (lane >= d) w += t;
        }
        wsum[lane] = w;
    }
    __syncthreads();
    int add = (wid > 0) ? wsum[wid - 1] : 0;
    int incl = v + add;
    int total = wsum[31];

    __shared__ int s_exc;
    if (threadIdx.x == 0) {
        unsigned long long flag = (b == 0) ? 2ULL : 1ULL;
        atomicExch(&g_lk[tw][b], (flag << 32) | (unsigned)total);
        int exc = 0;
        if (b > 0) {
            int p = b - 1;
            while (true) {
                unsigned long long pv = *((volatile unsigned long long*)&g_lk[tw][p]);
                unsigned f = (unsigned)(pv >> 32);
                if (f == 2u) { exc += (int)(unsigned)pv; break; }
                if (f == 1u) { exc += (int)(unsigned)pv; p--; }
            }
            atomicExch(&g_lk[tw][b], (2ULL << 32) | (unsigned)(total + exc));
        }
        s_exc = exc;
    }
    __syncthreads();
    if (i < NN) {
        g_off[tw][i] = s_exc + incl - c;
        float deg = 2.0f + (float)(unsigned)dc * (1.0f / DEG_SCALE);
        g_dinv[tw][i] = rsqrtf(deg);
    }
    if (b == gridDim.x - 1 && threadIdx.x == 0) g_off[tw][NN] = EE;
}

// ---------------------------------------------------------------------------
// fill: atomic-free, 4 edges per thread (vectorized coalesced loads)
// ---------------------------------------------------------------------------
__global__ void k_fill(const int* __restrict__ ei1, const float* __restrict__ ew1,
                       const int* __restrict__ ei2, const float* __restrict__ ew2) {
    int tw = blockIdx.y;
    const int*   ei = tw ? ei2 : ei1;
    const float* ew = tw ? ew2 : ew1;
    int e0 = (blockIdx.x * 256 + threadIdx.x) * 4;
    if (e0 >= EE) return;
    int4   sv = *(const int4*)(ei + e0);
    int4   dv = *(const int4*)(ei + EE + e0);
    float4 wv = *(const float4*)(ew + e0);
    int4   rv = *(const int4*)(g_rank[tw] + e0);
    const float* dinv = g_dinv[tw];
    int2* edge = g_edge[tw];
    const int* off = g_off[tw];
    {
        float nrm = dinv[sv.x] * fmaxf(wv.x, 0.0f) * dinv[dv.x];
        __half2 nh = __float2half2_rn(nrm);
        edge[off[dv.x] + rv.x] = make_int2(sv.x, *(int*)&nh);
    }
    {
        float nrm = dinv[sv.y] * fmaxf(wv.y, 0.0f) * dinv[dv.y];
        __half2 nh = __float2half2_rn(nrm);
        edge[off[dv.y] + rv.y] = make_int2(sv.y, *(int*)&nh);
    }
    {
        float nrm = dinv[sv.z] * fmaxf(wv.z, 0.0f) * dinv[dv.z];
        __half2 nh = __float2half2_rn(nrm);
        edge[off[dv.z] + rv.z] = make_int2(sv.z, *(int*)&nh);
    }
    {
        float nrm = dinv[sv.w] * fmaxf(wv.w, 0.0f) * dinv[dv.w];
        __half2 nh = __float2half2_rn(nrm);
        edge[off[dv.w] + rv.w] = make_int2(sv.w, *(int*)&nh);
    }
}

__global__ void k_gemm2(const float* __restrict__ W2) {
    int tw = blockIdx.z;
    gemm_body<O1, O2>(g_z1[tw], W2, g_h2h[tw],
                      blockIdx.x, blockIdx.y * 64, threadIdx.y * 16 + threadIdx.x);
}

// ---------------------------------------------------------------------------
// Aggregation 1: 4 nodes per warp (8 lanes each, uint4 = 8 fp16 per lane)
// ---------------------------------------------------------------------------
__global__ void __launch_bounds__(256, 8)
k_aggr1(const float* __restrict__ b1) {
    int tw    = blockIdx.y;
    int gwarp = (blockIdx.x * blockDim.x + threadIdx.x) >> 5;
    int lane  = threadIdx.x & 31;
    int node  = gwarp * 4 + (lane >> 3);
    int ln    = lane & 7;
    if (node >= NN) return;
    const int2*   eg = g_edge[tw];
    const __half* h  = g_h1h[tw];
    int beg = g_off[tw][node];
    int end = g_off[tw][node + 1];
    float dv = g_dinv[tw][node];
    __half2 slh = __float2half2_rn(2.0f * dv * dv);
    uint4 selfpk = *(const uint4*)(h + (size_t)node * O1 + ln * 8);
    __half2 mA = __hmul2(*(__half2*)&selfpk.x, slh);
    __half2 mB = __hmul2(*(__half2*)&selfpk.y, slh);
    __half2 mC = __hmul2(*(__half2*)&selfpk.z, slh);
    __half2 mD = __hmul2(*(__half2*)&selfpk.w, slh);
    int j = beg;
    for (; j + 4 <= end; j += 4) {
        int2 e0 = eg[j], e1 = eg[j + 1], e2 = eg[j + 2], e3 = eg[j + 3];
        uint4 v0 = *(const uint4*)(h + (size_t)e0.x * O1 + ln * 8);
        uint4 v1 = *(const uint4*)(h + (size_t)e1.x * O1 + ln * 8);
        uint4 v2 = *(const uint4*)(h + (size_t)e2.x * O1 + ln * 8);
        uint4 v3 = *(const uint4*)(h + (size_t)e3.x * O1 + ln * 8);
        __half2 w0 = *(__half2*)&e0.y, w1 = *(__half2*)&e1.y;
        __half2 w2 = *(__half2*)&e2.y, w3 = *(__half2*)&e3.y;
        mA = __hmax2(mA, __hmul2(*(__half2*)&v0.x, w0));
        mB = __hmax2(mB, __hmul2(*(__half2*)&v0.y, w0));
        mC = __hmax2(mC, __hmul2(*(__half2*)&v0.z, w0));
        mD = __hmax2(mD, __hmul2(*(__half2*)&v0.w, w0));
        mA = __hmax2(mA, __hmul2(*(__half2*)&v1.x, w1));
        mB = __hmax2(mB, __hmul2(*(__half2*)&v1.y, w1));
        mC = __hmax2(mC, __hmul2(*(__half2*)&v1.z, w1));
        mD = __hmax2(mD, __hmul2(*(__half2*)&v1.w, w1));
        mA = __hmax2(mA, __hmul2(*(__half2*)&v2.x, w2));
        mB = __hmax2(mB, __hmul2(*(__half2*)&v2.y, w2));
        mC = __hmax2(mC, __hmul2(*(__half2*)&v2.z, w2));
        mD = __hmax2(mD, __hmul2(*(__half2*)&v2.w, w2));
        mA = __hmax2(mA, __hmul2(*(__half2*)&v3.x, w3));
        mB = __hmax2(mB, __hmul2(*(__half2*)&v3.y, w3));
        mC = __hmax2(mC, __hmul2(*(__half2*)&v3.z, w3));
        mD = __hmax2(mD, __hmul2(*(__half2*)&v3.w, w3));
    }
    for (; j < end; j++) {
        int2 e = eg[j];
        uint4 v = *(const uint4*)(h + (size_t)e.x * O1 + ln * 8);
        __half2 wh = *(__half2*)&e.y;
        mA = __hmax2(mA, __hmul2(*(__half2*)&v.x, wh));
        mB = __hmax2(mB, __hmul2(*(__half2*)&v.y, wh));
        mC = __hmax2(mC, __hmul2(*(__half2*)&v.z, wh));
        mD = __hmax2(mD, __hmul2(*(__half2*)&v.w, wh));
    }
    float2 fA = __half22float2(mA);
    float2 fB = __half22float2(mB);
    float2 fC = __half22float2(mC);
    float2 fD = __half22float2(mD);
    float m[8] = {fA.x, fA.y, fB.x, fB.y, fC.x, fC.y, fD.x, fD.y};
#pragma unroll
    for (int q = 0; q < 8; q++)
        if (!isfinite(m[q])) m[q] = 0.0f;
    float4 bv0 = *(const float4*)(b1 + ln * 8);
    float4 bv1 = *(const float4*)(b1 + ln * 8 + 4);
    float* dst = g_z1[tw] + (size_t)node * O1 + ln * 8;
    *(float4*)(dst)     = make_float4(m[0] + bv0.x, m[1] + bv0.y, m[2] + bv0.z, m[3] + bv0.w);
    *(float4*)(dst + 4) = make_float4(m[4] + bv1.x, m[5] + bv1.y, m[6] + bv1.z, m[7] + bv1.w);
}

// ---------------------------------------------------------------------------
// Aggregation 2: 2 nodes per warp (16 lanes each, uint4 = 8 fp16 per lane);
// tail blocks reset g_dc / g_lk for the next invocation
// ---------------------------------------------------------------------------
__device__ __forceinline__ void max8_half(__half2& mA, __half2& mB, __half2& mC, __half2& mD,
                                          uint4 pk, __half2 wh) {
    mA = __hmax2(mA, __hmul2(*(__half2*)&pk.x, wh));
    mB = __hmax2(mB, __hmul2(*(__half2*)&pk.y, wh));
    mC = __hmax2(mC, __hmul2(*(__half2*)&pk.z, wh));
    mD = __hmax2(mD, __hmul2(*(__half2*)&pk.w, wh));
}

__global__ void __launch_bounds__(256, 8)
k_aggr2(const float* __restrict__ b2, float* __restrict__ out) {
    int tw = blockIdx.y;
    if (blockIdx.x >= AGG_BLOCKS) {
        int rb  = blockIdx.x - AGG_BLOCKS;
        int idx = (rb * 256 + threadIdx.x) * 2;
        if (idx     < NN) g_dc[tw][idx]     = 0ULL;
        if (idx + 1 < NN) g_dc[tw][idx + 1] = 0ULL;
        if (rb == 0 && threadIdx.x < 64) g_lk[tw][threadIdx.x] = 0ULL;
        return;
    }
    int gwarp = (blockIdx.x * blockDim.x + threadIdx.x) >> 5;
    int lane  = threadIdx.x & 31;
    int node  = gwarp * 2 + (lane >> 4);
    int ln    = lane & 15;
    if (node >= NN) return;
    const int2*   eg = g_edge[tw];
    const __half* h  = g_h2h[tw];
    float* op = out + (size_t)tw * NN * O2;
    int beg = g_off[tw][node];
    int end = g_off[tw][node + 1];
    float dv = g_dinv[tw][node];
    __half2 slh = __float2half2_rn(2.0f * dv * dv);
    uint4 selfpk = *(const uint4*)(h + (size_t)node * O2 + ln * 8);
    __half2 mA = __hmul2(*(__half2*)&selfpk.x, slh);
    __half2 mB = __hmul2(*(__half2*)&selfpk.y, slh);
    __half2 mC = __hmul2(*(__half2*)&selfpk.z, slh);
    __half2 mD = __hmul2(*(__half2*)&selfpk.w, slh);
    int j = beg;
    for (; j + 4 <= end; j += 4) {
        int2 e0 = eg[j], e1 = eg[j + 1], e2 = eg[j + 2], e3 = eg[j + 3];
        uint4 v0 = *(const uint4*)(h + (size_t)e0.x * O2 + ln * 8);
        uint4 v1 = *(const uint4*)(h + (size_t)e1.x * O2 + ln * 8);
        uint4 v2 = *(const uint4*)(h + (size_t)e2.x * O2 + ln * 8);
        uint4 v3 = *(const uint4*)(h + (size_t)e3.x * O2 + ln * 8);
        max8_half(mA, mB, mC, mD, v0, *(__half2*)&e0.y);
        max8_half(mA, mB, mC, mD, v1, *(__half2*)&e1.y);
        max8_half(mA, mB, mC, mD, v2, *(__half2*)&e2.y);
        max8_half(mA, mB, mC, mD, v3, *(__half2*)&e3.y);
    }
    for (; j < end; j++) {
        int2 e = eg[j];
        uint4 v = *(const uint4*)(h + (size_t)e.x * O2 + ln * 8);
        max8_half(mA, mB, mC, mD, v, *(__half2*)&e.y);
    }
    float2 fA = __half22float2(mA);
    float2 fB = __half22float2(mB);
    float2 fC = __half22float2(mC);
    float2 fD = __half22float2(mD);
    float m[8] = {fA.x, fA.y, fB.x, fB.y, fC.x, fC.y, fD.x, fD.y};
#pragma unroll
    for (int q = 0; q < 8; q++)
        if (!isfinite(m[q])) m[q] = 0.0f;
    float4 bv0 = *(const float4*)(b2 + ln * 8);
    float4 bv1 = *(const float4*)(b2 + ln * 8 + 4);
    float* dst = op + (size_t)node * O2 + ln * 8;
    *(float4*)(dst)     = make_float4(m[0] + bv0.x, m[1] + bv0.y, m[2] + bv0.z, m[3] + bv0.w);
    *(float4*)(dst + 4) = make_float4(m[4] + bv1.x, m[5] + bv1.y, m[6] + bv1.z, m[7] + bv1.w);
}

// ---------------------------------------------------------------------------
// launch
// ---------------------------------------------------------------------------
extern "C" void kernel_launch(void* const* d_in, const int* in_sizes, int n_in,
                              void* d_out, int out_size) {
    const float* x1  = (const float*)d_in[0];
    const int*   ei1 = (const int*)  d_in[1];
    const float* ew1 = (const float*)d_in[2];
    const float* x2  = (const float*)d_in[3];
    const int*   ei2 = (const int*)  d_in[4];
    const float* ew2 = (const float*)d_in[5];
    const float* W1  = (const float*)d_in[6];
    const float* b1  = (const float*)d_in[7];
    const float* W2  = (const float*)d_in[8];
    const float* b2  = (const float*)d_in[9];
    float* out = (float*)d_out;

    const int TB = 256;
    k_prep_gemm1<<<dim3(G1_BLOCKS + PREP_BLOCKS, 2), TB>>>(ei1, ew1, ei2, ew2, x1, x2, W1);
    k_scan      <<<dim3(NBLK, 2), SCAN_B>>>();
    k_fill      <<<dim3(FILL_BLOCKS, 2), TB>>>(ei1, ew1, ei2, ew2);

    k_aggr1<<<dim3(AGG1_BLOCKS, 2), TB>>>(b1);
    dim3 gblk(16, 16);
    k_gemm2<<<dim3(G1_BLOCKS, 2, 2), gblk>>>(W2);
    k_aggr2<<<dim3(AGG_BLOCKS + RST_BLOCKS, 2), TB>>>(b2, out);
}